// round 1
// baseline (speedup 1.0000x reference)
#include <cuda_runtime.h>
#include <cuda_fp16.h>
#include <stdint.h>

// WindowAttention: B_=4096 windows, N=49 tokens, H=8 heads, hd=32, DIM=256.
// q = k = v = x (reference uses x_qkv[0] for all three).
// S = scale*(q@q^T) + bias[h] + mask[w]; P = softmax(S); out = P@q.
//
// Strategy: HMMA mma.sync.m16n8k16 (f16 in, f32 acc).
//  - fp16 hi/lo split of x for the S GEMM (3 MMAs) -> logit error ~1e-6.
//  - plain fp16 V for P@V -> output error ~3e-4 (dominated by P fp16 pack).
//  - bias gathered per-fragment-element from smem table via u8 rel-index.
//  - 1 CTA per b; warp = head; 4 row-quarters (m16); cols padded 49->56 (7 n8 tiles).

#define NTOK 49
#define NPAD 64
#define NHEAD 8
#define HD 32
#define DIMC 256
#define XSTR 264   // half stride per row of x tiles (conflict-free fragment loads)
#define MSTR 66    // float stride for mask plane
#define RSTR 68    // byte stride for rel-index plane

struct SmemLayout {
  __half  xhi[NPAD * XSTR];     // 33792 B
  __half  xlo[NPAD * XSTR];     // 33792 B
  float   smask[NPAD * MSTR];   // 16896 B
  float   sbt[NHEAD * 169];     //  5408 B  (bias_table transposed: [h][idx])
  uint8_t srel[NPAD * RSTR];    //  4352 B
};                              // total 94240 B -> 2 CTAs/SM

__device__ __forceinline__ void mma16816(float* c, const uint32_t* a, uint32_t b0, uint32_t b1) {
  asm volatile(
      "mma.sync.aligned.m16n8k16.row.col.f32.f16.f16.f32 "
      "{%0,%1,%2,%3},{%4,%5,%6,%7},{%8,%9},{%0,%1,%2,%3};\n"
      : "+f"(c[0]), "+f"(c[1]), "+f"(c[2]), "+f"(c[3])
      : "r"(a[0]), "r"(a[1]), "r"(a[2]), "r"(a[3]), "r"(b0), "r"(b1));
}

__device__ __forceinline__ uint32_t pack2f(float a, float b) {
  __half2 h = __floats2half2_rn(a, b);
  return *reinterpret_cast<uint32_t*>(&h);
}
__device__ __forceinline__ uint32_t pack2h(__half a, __half b) {
  __half2 h = __halves2half2(a, b);
  return *reinterpret_cast<uint32_t*>(&h);
}

__global__ void __launch_bounds__(256, 2)
winattn_kernel(const float* __restrict__ x, const float* __restrict__ bias_table,
               const float* __restrict__ mask, const int* __restrict__ rel,
               float* __restrict__ out) {
  extern __shared__ char smraw[];
  SmemLayout* sm = reinterpret_cast<SmemLayout*>(smraw);
  const int tid = threadIdx.x;
  const int b = blockIdx.x;
  const int w = b & 63;  // b = img*64 + w

  // ---- fill shared memory ----
  {  // zero pad rows [49,64) of xhi/xlo (read by MMA fragments, must be 0)
    uint32_t* ph = reinterpret_cast<uint32_t*>(sm->xhi + NTOK * XSTR);
    uint32_t* pl = reinterpret_cast<uint32_t*>(sm->xlo + NTOK * XSTR);
    const int n32 = (NPAD - NTOK) * XSTR / 2;
    for (int i = tid; i < n32; i += 256) { ph[i] = 0u; pl[i] = 0u; }
  }
  {  // x -> fp16 hi/lo split
    const float2* x2 = reinterpret_cast<const float2*>(x) + (size_t)b * NTOK * (DIMC / 2);
    for (int idx = tid; idx < NTOK * (DIMC / 2); idx += 256) {
      int r = idx >> 7, c2 = idx & 127;
      float2 v = x2[idx];
      __half hx = __float2half_rn(v.x), hy = __float2half_rn(v.y);
      float lx = v.x - __half2float(hx), ly = v.y - __half2float(hy);
      int off = r * XSTR + c2 * 2;
      *reinterpret_cast<__half2*>(sm->xhi + off) = __halves2half2(hx, hy);
      *reinterpret_cast<__half2*>(sm->xlo + off) =
          __halves2half2(__float2half_rn(lx), __float2half_rn(ly));
    }
  }
  for (int idx = tid; idx < NPAD * NPAD; idx += 256) {
    int i = idx >> 6, j = idx & 63;
    bool valid = (i < NTOK) && (j < NTOK);
    sm->smask[i * MSTR + j] = valid ? mask[(w * NTOK + i) * NTOK + j] : -1e9f;
    sm->srel[i * RSTR + j] = valid ? (uint8_t)rel[i * NTOK + j] : (uint8_t)0;
  }
  for (int idx = tid; idx < 169 * NHEAD; idx += 256) {
    int r = idx >> 3, h = idx & 7;
    sm->sbt[h * 169 + r] = bias_table[idx];  // bias_table is (169, 8)
  }
  __syncthreads();

  const int warp = tid >> 5, lane = tid & 31;
  const int g = lane >> 2, t = lane & 3;
  const int h = warp;
  const float scale = 0.17677669529663687f;  // 32^-0.5
  const __half* xh = sm->xhi;
  const __half* xl = sm->xlo;
  const float* bt = sm->sbt + h * 169;
  float* outb = out + (size_t)b * NTOK * DIMC;

#pragma unroll 1
  for (int rq = 0; rq < 4; rq++) {
    const int q0 = rq * 16;
    // Q A-fragments (m16k16, rows q0..q0+15, k = head dims 0..31)
    uint32_t qhi[2][4], qlo[2][4];
#pragma unroll
    for (int kt = 0; kt < 2; kt++) {
      const int cb = h * HD + kt * 16 + t * 2;
      const int r0 = (q0 + g) * XSTR + cb, r1 = (q0 + g + 8) * XSTR + cb;
      qhi[kt][0] = *reinterpret_cast<const uint32_t*>(xh + r0);
      qhi[kt][1] = *reinterpret_cast<const uint32_t*>(xh + r1);
      qhi[kt][2] = *reinterpret_cast<const uint32_t*>(xh + r0 + 8);
      qhi[kt][3] = *reinterpret_cast<const uint32_t*>(xh + r1 + 8);
      qlo[kt][0] = *reinterpret_cast<const uint32_t*>(xl + r0);
      qlo[kt][1] = *reinterpret_cast<const uint32_t*>(xl + r1);
      qlo[kt][2] = *reinterpret_cast<const uint32_t*>(xl + r0 + 8);
      qlo[kt][3] = *reinterpret_cast<const uint32_t*>(xl + r1 + 8);
    }
    float sc[8][4];
#pragma unroll
    for (int i = 0; i < 8; i++)
#pragma unroll
      for (int k = 0; k < 4; k++) sc[i][k] = 0.f;

    // S = q*k^T with hi/lo split (cols padded to 56: 7 n8 tiles)
#pragma unroll
    for (int nt = 0; nt < 7; nt++) {
      const int jr = (nt * 8 + g) * XSTR;
#pragma unroll
      for (int kt = 0; kt < 2; kt++) {
        const int cb = h * HD + kt * 16 + t * 2;
        uint32_t bh0 = *reinterpret_cast<const uint32_t*>(xh + jr + cb);
        uint32_t bh1 = *reinterpret_cast<const uint32_t*>(xh + jr + cb + 8);
        uint32_t bl0 = *reinterpret_cast<const uint32_t*>(xl + jr + cb);
        uint32_t bl1 = *reinterpret_cast<const uint32_t*>(xl + jr + cb + 8);
        mma16816(sc[nt], qhi[kt], bh0, bh1);
        mma16816(sc[nt], qhi[kt], bl0, bl1);
        mma16816(sc[nt], qlo[kt], bh0, bh1);
      }
    }

    // scale + bias + mask, rowwise softmax (rows g and g+8 of this m16 tile)
    const int i0 = q0 + g, i1 = i0 + 8;
    float mx0 = -1e30f, mx1 = -1e30f;
#pragma unroll
    for (int nt = 0; nt < 7; nt++) {
      const int j = nt * 8 + t * 2;
      float2 mA = *reinterpret_cast<const float2*>(sm->smask + i0 * MSTR + j);
      float2 mB = *reinterpret_cast<const float2*>(sm->smask + i1 * MSTR + j);
      const uint8_t* rA = sm->srel + i0 * RSTR + j;
      const uint8_t* rB = sm->srel + i1 * RSTR + j;
      float s0 = fmaf(sc[nt][0], scale, mA.x + bt[rA[0]]);
      float s1 = fmaf(sc[nt][1], scale, mA.y + bt[rA[1]]);
      float s2 = fmaf(sc[nt][2], scale, mB.x + bt[rB[0]]);
      float s3 = fmaf(sc[nt][3], scale, mB.y + bt[rB[1]]);
      sc[nt][0] = s0; sc[nt][1] = s1; sc[nt][2] = s2; sc[nt][3] = s3;
      mx0 = fmaxf(mx0, fmaxf(s0, s1));
      mx1 = fmaxf(mx1, fmaxf(s2, s3));
    }
    mx0 = fmaxf(mx0, __shfl_xor_sync(0xffffffffu, mx0, 1));
    mx0 = fmaxf(mx0, __shfl_xor_sync(0xffffffffu, mx0, 2));
    mx1 = fmaxf(mx1, __shfl_xor_sync(0xffffffffu, mx1, 1));
    mx1 = fmaxf(mx1, __shfl_xor_sync(0xffffffffu, mx1, 2));
    float sum0 = 0.f, sum1 = 0.f;
#pragma unroll
    for (int nt = 0; nt < 7; nt++) {
      float e0 = __expf(sc[nt][0] - mx0);
      float e1 = __expf(sc[nt][1] - mx0);
      float e2 = __expf(sc[nt][2] - mx1);
      float e3 = __expf(sc[nt][3] - mx1);
      sc[nt][0] = e0; sc[nt][1] = e1; sc[nt][2] = e2; sc[nt][3] = e3;
      sum0 += e0 + e1; sum1 += e2 + e3;
    }
    sum0 += __shfl_xor_sync(0xffffffffu, sum0, 1);
    sum0 += __shfl_xor_sync(0xffffffffu, sum0, 2);
    sum1 += __shfl_xor_sync(0xffffffffu, sum1, 1);
    sum1 += __shfl_xor_sync(0xffffffffu, sum1, 2);
    const float rn0 = 1.f / sum0, rn1 = 1.f / sum1;

    // O = P @ V   (K=64 over j: 4 k16 tiles; sc[7] stays zero -> P=0 for j>=56)
    float oc[4][4];
#pragma unroll
    for (int i = 0; i < 4; i++)
#pragma unroll
      for (int k = 0; k < 4; k++) oc[i][k] = 0.f;

#pragma unroll
    for (int kt = 0; kt < 4; kt++) {
      const float* sA = sc[2 * kt];
      const float* sB = sc[2 * kt + 1];
      uint32_t pa[4];
      pa[0] = pack2f(sA[0] * rn0, sA[1] * rn0);
      pa[1] = pack2f(sA[2] * rn1, sA[3] * rn1);
      pa[2] = pack2f(sB[0] * rn0, sB[1] * rn0);
      pa[3] = pack2f(sB[2] * rn1, sB[3] * rn1);
      const int j0 = kt * 16 + t * 2;
#pragma unroll
      for (int nt2 = 0; nt2 < 4; nt2++) {
        const int col = h * HD + nt2 * 8 + g;
        __half v0 = xh[(j0    ) * XSTR + col];
        __half v1 = xh[(j0 + 1) * XSTR + col];
        __half v2 = xh[(j0 + 8) * XSTR + col];
        __half v3 = xh[(j0 + 9) * XSTR + col];
        mma16816(oc[nt2], pa, pack2h(v0, v1), pack2h(v2, v3));
      }
    }

    // store valid rows (float2, sector-aligned)
    if (i0 < NTOK) {
#pragma unroll
      for (int nt2 = 0; nt2 < 4; nt2++) {
        float2 v; v.x = oc[nt2][0]; v.y = oc[nt2][1];
        *reinterpret_cast<float2*>(outb + (size_t)i0 * DIMC + h * HD + nt2 * 8 + t * 2) = v;
      }
    }
    if (i1 < NTOK) {
#pragma unroll
      for (int nt2 = 0; nt2 < 4; nt2++) {
        float2 v; v.x = oc[nt2][2]; v.y = oc[nt2][3];
        *reinterpret_cast<float2*>(outb + (size_t)i1 * DIMC + h * HD + nt2 * 8 + t * 2) = v;
      }
    }
  }
}

extern "C" void kernel_launch(void* const* d_in, const int* in_sizes, int n_in,
                              void* d_out, int out_size) {
  (void)in_sizes; (void)n_in; (void)out_size;
  const float* x = (const float*)d_in[0];
  const float* bias_table = (const float*)d_in[1];
  const float* mask = (const float*)d_in[2];
  const int* rel = (const int*)d_in[3];
  float* out = (float*)d_out;

  size_t shmem = sizeof(SmemLayout);
  cudaFuncSetAttribute(winattn_kernel, cudaFuncAttributeMaxDynamicSharedMemorySize, (int)shmem);
  winattn_kernel<<<4096, 256, shmem>>>(x, bias_table, mask, rel, out);
}

// round 2
// speedup vs baseline: 1.8296x; 1.8296x over previous
#include <cuda_runtime.h>
#include <cuda_fp16.h>
#include <stdint.h>

// WindowAttention, GB300. B_=4096 windows, N=49, H=8, hd=32, q=k=v=x.
// Round 2: pure-fp16 S-GEMM (no hi/lo split), ldmatrix fragment loads,
// fused (mask+bias)*log2e precomputed into a device-global plane [w][h][64][56],
// 3 CTAs/SM (static smem = x-fp16 plane only, 33.8KB).

#define NTOK 49
#define NPAD 64
#define NHEAD 8
#define HD 32
#define DIMC 256
#define XSTR 264   // half stride per row (conflict-free ldmatrix: 528B = 132 words, 132%32=4)
#define FJ 56      // fused plane row width (padded cols)
#define FI 64      // fused plane rows (padded rows)

// fused[(w*8+h)*FI*FJ + i*FJ + j] = (mask[w,i,j] + bias_table[rel[i,j], h]) * log2(e)
__device__ float g_fused[64 * NHEAD * FI * FJ];   // 7.34 MB, L2-resident

__global__ void precompute_fused(const float* __restrict__ bias_table,
                                 const float* __restrict__ mask,
                                 const int* __restrict__ rel) {
  const int w = blockIdx.x >> 3, h = blockIdx.x & 7;
  float* outp = g_fused + (size_t)blockIdx.x * FI * FJ;
  for (int idx = threadIdx.x; idx < FI * FJ; idx += blockDim.x) {
    int i = idx / FJ, j = idx - i * FJ;
    float v = -1e9f;
    if (i < NTOK && j < NTOK)
      v = (mask[(w * NTOK + i) * NTOK + j] +
           bias_table[rel[i * NTOK + j] * NHEAD + h]) * 1.4426950408889634f;
    outp[idx] = v;
  }
}

__device__ __forceinline__ void mma16816(float* c, const uint32_t* a, uint32_t b0, uint32_t b1) {
  asm volatile(
      "mma.sync.aligned.m16n8k16.row.col.f32.f16.f16.f32 "
      "{%0,%1,%2,%3},{%4,%5,%6,%7},{%8,%9},{%0,%1,%2,%3};\n"
      : "+f"(c[0]), "+f"(c[1]), "+f"(c[2]), "+f"(c[3])
      : "r"(a[0]), "r"(a[1]), "r"(a[2]), "r"(a[3]), "r"(b0), "r"(b1));
}

__device__ __forceinline__ void ldsm_x4(uint32_t& r0, uint32_t& r1, uint32_t& r2, uint32_t& r3,
                                        uint32_t addr) {
  asm volatile("ldmatrix.sync.aligned.m8n8.x4.shared.b16 {%0,%1,%2,%3},[%4];\n"
               : "=r"(r0), "=r"(r1), "=r"(r2), "=r"(r3) : "r"(addr));
}
__device__ __forceinline__ void ldsm_x4_t(uint32_t& r0, uint32_t& r1, uint32_t& r2, uint32_t& r3,
                                          uint32_t addr) {
  asm volatile("ldmatrix.sync.aligned.m8n8.x4.trans.shared.b16 {%0,%1,%2,%3},[%4];\n"
               : "=r"(r0), "=r"(r1), "=r"(r2), "=r"(r3) : "r"(addr));
}

__device__ __forceinline__ uint32_t pack2f(float a, float b) {
  __half2 h = __floats2half2_rn(a, b);
  return *reinterpret_cast<uint32_t*>(&h);
}
__device__ __forceinline__ float ex2(float x) {
  float r;
  asm("ex2.approx.ftz.f32 %0, %1;\n" : "=f"(r) : "f"(x));
  return r;
}

__global__ void __launch_bounds__(256, 3)
winattn_kernel(const float* __restrict__ x, float* __restrict__ out) {
  __shared__ __half xh[NPAD * XSTR];   // 33792 B -> 3 CTAs/SM
  const int tid = threadIdx.x;
  const int b = blockIdx.x;
  const int w = b & 63;   // b = img*64 + w

  // ---- fill: x -> fp16 plane, zero the pad rows ----
  {
    uint32_t* p = reinterpret_cast<uint32_t*>(xh + NTOK * XSTR);
    const int n32 = (NPAD - NTOK) * XSTR / 2;
    for (int i = tid; i < n32; i += 256) p[i] = 0u;
  }
  {
    const float2* x2 = reinterpret_cast<const float2*>(x) + (size_t)b * NTOK * (DIMC / 2);
    for (int idx = tid; idx < NTOK * (DIMC / 2); idx += 256) {
      int r = idx >> 7, c2 = idx & 127;
      float2 v = x2[idx];
      *reinterpret_cast<__half2*>(xh + r * XSTR + c2 * 2) = __float22half2_rn(v);
    }
  }
  __syncthreads();

  const int lane = tid & 31;
  const int g = lane >> 2, t = lane & 3;
  const int h = tid >> 5;                  // warp = head
  const int lr = lane & 7, lm = lane >> 3; // ldmatrix row-in-matrix / matrix id
  const uint32_t smbase = (uint32_t)__cvta_generic_to_shared(xh);
  const float* fb = g_fused + (size_t)(w * NHEAD + h) * FI * FJ;
  float* outb = out + (size_t)b * NTOK * DIMC + h * HD;
  const float SL2E = 0.25503480f;          // 32^-0.5 * log2(e)

#pragma unroll 1
  for (int rq = 0; rq < 4; rq++) {
    const int q0 = rq * 16;
    const int i0 = q0 + g, i1 = i0 + 8;

    // prefetch fused bias+mask rows (L2 hits, issued before the MMA loop)
    float2 fA[7], fB[7];
#pragma unroll
    for (int nt = 0; nt < 7; nt++) {
      fA[nt] = *reinterpret_cast<const float2*>(fb + i0 * FJ + nt * 8 + t * 2);
      fB[nt] = *reinterpret_cast<const float2*>(fb + i1 * FJ + nt * 8 + t * 2);
    }

    // Q A-fragments: one ldmatrix.x4 per kt
    uint32_t qa[2][4];
#pragma unroll
    for (int kt = 0; kt < 2; kt++) {
      uint32_t a = smbase +
          (((q0 + ((lm & 1) << 3) + lr) * XSTR + h * HD + kt * 16 + ((lm >> 1) << 3)) << 1);
      ldsm_x4(qa[kt][0], qa[kt][1], qa[kt][2], qa[kt][3], a);
    }

    float sc[7][4];
#pragma unroll
    for (int i = 0; i < 7; i++)
#pragma unroll
      for (int k = 0; k < 4; k++) sc[i][k] = 0.f;

    // S = x @ x^T (fp16), K B-fragments: one ldmatrix.x4 per nt (covers both kt)
#pragma unroll
    for (int nt = 0; nt < 7; nt++) {
      uint32_t k0, k1, k2, k3;
      uint32_t a = smbase + (((nt * 8 + lr) * XSTR + h * HD + lm * 8) << 1);
      ldsm_x4(k0, k1, k2, k3, a);
      mma16816(sc[nt], qa[0], k0, k1);
      mma16816(sc[nt], qa[1], k2, k3);
    }

    // softmax (log2 domain: fused already has *log2e, SL2E = scale*log2e)
    float mx0 = -1e30f, mx1 = -1e30f;
#pragma unroll
    for (int nt = 0; nt < 7; nt++) {
      float s0 = fmaf(sc[nt][0], SL2E, fA[nt].x);
      float s1 = fmaf(sc[nt][1], SL2E, fA[nt].y);
      float s2 = fmaf(sc[nt][2], SL2E, fB[nt].x);
      float s3 = fmaf(sc[nt][3], SL2E, fB[nt].y);
      sc[nt][0] = s0; sc[nt][1] = s1; sc[nt][2] = s2; sc[nt][3] = s3;
      mx0 = fmaxf(mx0, fmaxf(s0, s1));
      mx1 = fmaxf(mx1, fmaxf(s2, s3));
    }
    mx0 = fmaxf(mx0, __shfl_xor_sync(0xffffffffu, mx0, 1));
    mx0 = fmaxf(mx0, __shfl_xor_sync(0xffffffffu, mx0, 2));
    mx1 = fmaxf(mx1, __shfl_xor_sync(0xffffffffu, mx1, 1));
    mx1 = fmaxf(mx1, __shfl_xor_sync(0xffffffffu, mx1, 2));
    float sum0 = 0.f, sum1 = 0.f;
#pragma unroll
    for (int nt = 0; nt < 7; nt++) {
      float e0 = ex2(sc[nt][0] - mx0);
      float e1 = ex2(sc[nt][1] - mx0);
      float e2 = ex2(sc[nt][2] - mx1);
      float e3 = ex2(sc[nt][3] - mx1);
      sc[nt][0] = e0; sc[nt][1] = e1; sc[nt][2] = e2; sc[nt][3] = e3;
      sum0 += e0 + e1; sum1 += e2 + e3;
    }
    sum0 += __shfl_xor_sync(0xffffffffu, sum0, 1);
    sum0 += __shfl_xor_sync(0xffffffffu, sum0, 2);
    sum1 += __shfl_xor_sync(0xffffffffu, sum1, 1);
    sum1 += __shfl_xor_sync(0xffffffffu, sum1, 2);
    const float rn0 = 1.f / sum0, rn1 = 1.f / sum1;

    // O = P @ V; V B-fragments via ldmatrix.x4.trans (2 per kt)
    float oc[4][4];
#pragma unroll
    for (int i = 0; i < 4; i++)
#pragma unroll
      for (int k = 0; k < 4; k++) oc[i][k] = 0.f;

    const float zz[4] = {0.f, 0.f, 0.f, 0.f};
#pragma unroll
    for (int kt = 0; kt < 4; kt++) {
      const float* sA = sc[2 * kt];
      const float* sB = (kt < 3) ? sc[2 * kt + 1] : zz;   // j>=56 tile: P = 0
      uint32_t pa[4];
      pa[0] = pack2f(sA[0] * rn0, sA[1] * rn0);
      pa[1] = pack2f(sA[2] * rn1, sA[3] * rn1);
      pa[2] = pack2f(sB[0] * rn0, sB[1] * rn0);
      pa[3] = pack2f(sB[2] * rn1, sB[3] * rn1);
#pragma unroll
      for (int ntb = 0; ntb < 2; ntb++) {
        uint32_t v0, v1, v2, v3;
        uint32_t a = smbase +
            (((kt * 16 + ((lm & 1) << 3) + lr) * XSTR + h * HD + (ntb * 2 + (lm >> 1)) * 8) << 1);
        ldsm_x4_t(v0, v1, v2, v3, a);
        mma16816(oc[ntb * 2 + 0], pa, v0, v1);
        mma16816(oc[ntb * 2 + 1], pa, v2, v3);
      }
    }

    // store valid rows
    if (i0 < NTOK) {
#pragma unroll
      for (int nt2 = 0; nt2 < 4; nt2++) {
        float2 v; v.x = oc[nt2][0]; v.y = oc[nt2][1];
        *reinterpret_cast<float2*>(outb + (size_t)i0 * DIMC + nt2 * 8 + t * 2) = v;
      }
    }
    if (i1 < NTOK) {
#pragma unroll
      for (int nt2 = 0; nt2 < 4; nt2++) {
        float2 v; v.x = oc[nt2][2]; v.y = oc[nt2][3];
        *reinterpret_cast<float2*>(outb + (size_t)i1 * DIMC + nt2 * 8 + t * 2) = v;
      }
    }
  }
}

extern "C" void kernel_launch(void* const* d_in, const int* in_sizes, int n_in,
                              void* d_out, int out_size) {
  (void)in_sizes; (void)n_in; (void)out_size;
  const float* x = (const float*)d_in[0];
  const float* bias_table = (const float*)d_in[1];
  const float* mask = (const float*)d_in[2];
  const int* rel = (const int*)d_in[3];
  float* out = (float*)d_out;

  precompute_fused<<<64 * NHEAD, 256>>>(bias_table, mask, rel);
  winattn_kernel<<<4096, 256>>>(x, out);
}